// round 10
// baseline (speedup 1.0000x reference)
#include <cuda_runtime.h>
#include <math.h>

#define NN 768
#define CS 384
#define CZ 128
#define CH 16
#define HH 12
#define PQK 4
#define PV 8
#define HC (HH*CH)        // 192
#define VP_DIM (HH*3*PV)  // 288
#define CATD 2112
#define OTOT 1152
#define INFV 100000.0f
#define SQRT13 0.57735026918962576f
#define EXT 32

// ------------------- scratch ------------------------------------------------
__device__ float g_raw[NN*OTOT];
__device__ float g_v[NN*HC];
__device__ float g_vpts[NN*VP_DIM];
__device__ float g_extq[NN*HH*EXT];
__device__ float g_extk[NN*HH*EXT];
__device__ float g_att[NN*HH*NN];   // [q][h][k]
__device__ float g_opt[NN*VP_DIM];
__device__ float g_cat[NN*CATD];

// ------------------- kernel 1: big projection GEMM --------------------------
struct WSrc { const float* w; const float* b; int lo; int F; };

__device__ __forceinline__ WSrc wmap(int o,
    const float* w_q, const float* b_q, const float* w_k, const float* b_k,
    const float* w_v, const float* b_v, const float* w_qp, const float* b_qp,
    const float* w_kp, const float* b_kp, const float* w_vp, const float* b_vp)
{
    WSrc r;
    if (o < 192)      { r.w = w_q;  r.b = b_q;  r.lo = o;       r.F = 192; }
    else if (o < 384) { r.w = w_k;  r.b = b_k;  r.lo = o - 192; r.F = 192; }
    else if (o < 576) { r.w = w_v;  r.b = b_v;  r.lo = o - 384; r.F = 192; }
    else if (o < 720) { r.w = w_qp; r.b = b_qp; r.lo = o - 576; r.F = 144; }
    else if (o < 864) { r.w = w_kp; r.b = b_kp; r.lo = o - 720; r.F = 144; }
    else              { r.w = w_vp; r.b = b_vp; r.lo = o - 864; r.F = 288; }
    return r;
}

__global__ void k_gproj(const float* __restrict__ s,
    const float* __restrict__ w_q, const float* __restrict__ b_q,
    const float* __restrict__ w_k, const float* __restrict__ b_k,
    const float* __restrict__ w_v, const float* __restrict__ b_v,
    const float* __restrict__ w_qp, const float* __restrict__ b_qp,
    const float* __restrict__ w_kp, const float* __restrict__ b_kp,
    const float* __restrict__ w_vp, const float* __restrict__ b_vp)
{
    __shared__ float a_t[32*68];
    __shared__ float b_t[32*68];
    __shared__ float bias_s[64];
    int n0 = blockIdx.x*64, o0 = blockIdx.y*64;
    int tid = threadIdx.x;                 // 256
    int tx = tid & 15, ty = tid >> 4;      // tx: 4 o (float4), ty: 4 n

    if (tid < 64) {
        WSrc m = wmap(o0 + tid, w_q,b_q,w_k,b_k,w_v,b_v,w_qp,b_qp,w_kp,b_kp,w_vp,b_vp);
        bias_s[tid] = m.b[m.lo];
    }

    float4 acc[4];
    #pragma unroll
    for (int i = 0; i < 4; ++i) acc[i] = make_float4(0.f,0.f,0.f,0.f);

    for (int kt = 0; kt < CS; kt += 32) {
        __syncthreads();
        for (int idx = tid; idx < 2048; idx += 256) {
            int nn = idx >> 5, kk = idx & 31;
            a_t[kk*68 + nn] = s[(n0+nn)*CS + kt + kk];
        }
        for (int idx = tid; idx < 2048; idx += 256) {
            int kk = idx >> 6, oo = idx & 63;
            WSrc m = wmap(o0 + oo, w_q,b_q,w_k,b_k,w_v,b_v,w_qp,b_qp,w_kp,b_kp,w_vp,b_vp);
            b_t[kk*68 + oo] = m.w[(kt+kk)*m.F + m.lo];
        }
        __syncthreads();
        #pragma unroll
        for (int kk = 0; kk < 32; ++kk) {
            float av[4];
            #pragma unroll
            for (int i = 0; i < 4; ++i) av[i] = a_t[kk*68 + ty*4 + i];
            float4 bv = *reinterpret_cast<const float4*>(&b_t[kk*68 + tx*4]);
            #pragma unroll
            for (int i = 0; i < 4; ++i) {
                acc[i].x += av[i]*bv.x; acc[i].y += av[i]*bv.y;
                acc[i].z += av[i]*bv.z; acc[i].w += av[i]*bv.w;
            }
        }
    }
    float4 bia = *reinterpret_cast<const float4*>(&bias_s[tx*4]);
    #pragma unroll
    for (int i = 0; i < 4; ++i) {
        int n = n0 + ty*4 + i;
        float4 r = acc[i];
        r.x += bia.x; r.y += bia.y; r.z += bia.z; r.w += bia.w;
        *reinterpret_cast<float4*>(&g_raw[n*OTOT + o0 + tx*4]) = r;
    }
}

// ------------------- kernel 1b: rigid transform + ext features --------------
__global__ void k_post(const float* __restrict__ rot, const float* __restrict__ trans,
                       const float* __restrict__ head_weights)
{
    __shared__ float raw[OTOT];
    __shared__ float rt_s[9], tr_s[3];
    __shared__ float qg[48*3], kg[48*3];
    __shared__ float q2p[48], k2p[48];
    __shared__ float q2s[12], k2s[12], pw_s[12];
    int n = blockIdx.x, tid = threadIdx.x;  // 256
    for (int i = tid; i < OTOT; i += 256) raw[i] = g_raw[n*OTOT + i];
    if (tid < 9) rt_s[tid] = rot[n*9 + tid];
    if (tid < 3) tr_s[tid] = trans[n*3 + tid];
    __syncthreads();

    if (tid < 192) g_v[n*HC + tid] = raw[384 + tid];

    if (tid < 192) {
        int it = tid;
        const float* src; int h, p, P; int tag;
        if (it < 48)      { src = raw + 576; h = it/4; p = it%4; P = 4; tag = 0; }
        else if (it < 96) { it -= 48; src = raw + 720; h = it/4; p = it%4; P = 4; tag = 1; }
        else              { it -= 96; src = raw + 864; h = it/8; p = it%8; P = 8; tag = 2; }
        float l0 = src[h*3*P + 0*P + p];
        float l1 = src[h*3*P + 1*P + p];
        float l2 = src[h*3*P + 2*P + p];
        float gx = rt_s[0]*l0 + rt_s[1]*l1 + rt_s[2]*l2 + tr_s[0];
        float gy = rt_s[3]*l0 + rt_s[4]*l1 + rt_s[5]*l2 + tr_s[1];
        float gz = rt_s[6]*l0 + rt_s[7]*l1 + rt_s[8]*l2 + tr_s[2];
        if (tag == 2) {
            int base = ((n*HH + h)*P + p)*3;
            g_vpts[base+0] = gx; g_vpts[base+1] = gy; g_vpts[base+2] = gz;
        } else {
            float* dst = (tag == 0) ? qg : kg;
            dst[(h*4+p)*3+0] = gx; dst[(h*4+p)*3+1] = gy; dst[(h*4+p)*3+2] = gz;
            float n2 = gx*gx + gy*gy + gz*gz;
            if (tag == 0) q2p[h*4+p] = n2; else k2p[h*4+p] = n2;
        }
    }
    __syncthreads();
    if (tid < 12) {
        q2s[tid] = q2p[tid*4] + q2p[tid*4+1] + q2p[tid*4+2] + q2p[tid*4+3];
        k2s[tid] = k2p[tid*4] + k2p[tid*4+1] + k2p[tid*4+2] + k2p[tid*4+3];
        float x = head_weights[tid];
        float sp = fmaxf(x, 0.f) + log1pf(expf(-fabsf(x)));
        pw_s[tid] = 0.23570226039551584f * sp;   // sqrt(2/36)*softplus
    }
    __syncthreads();

    for (int idx = tid; idx < HH*EXT; idx += 256) {
        int h = idx >> 5, j = idx & 31;
        float pw = pw_s[h];
        float eq = 0.f, ek = 0.f;
        if (j < 16) {
            eq = raw[h*16 + j] * 0.25f;
            ek = raw[192 + h*16 + j];
        } else if (j < 28) {
            int p = (j-16)/3, c = (j-16)%3;
            eq = pw * qg[(h*4+p)*3 + c];
            ek = kg[(h*4+p)*3 + c];
        } else if (j == 28) {
            eq = -0.5f * pw * q2s[h];  ek = 1.f;
        } else if (j == 29) {
            eq = 1.f;  ek = -0.5f * pw * k2s[h];
        }
        g_extq[n*HH*EXT + idx] = eq;
        g_extk[n*HH*EXT + idx] = ek;
    }
}

// ------------------- kernel 2: ext-dot (qk + point attention) ---------------
__global__ void k_qkpt(const float* __restrict__ b_b)
{
    __shared__ float eq_s[64*33];
    __shared__ float ek_s[64*33];
    int kt = blockIdx.x, qt = blockIdx.y, h = blockIdx.z;
    int q0 = qt*64, k0 = kt*64;
    int tid = threadIdx.x;              // 128
    for (int idx = tid; idx < 64*32; idx += 128) {
        int row = idx >> 5, j = idx & 31;
        eq_s[row*33 + j] = g_extq[(q0+row)*HH*EXT + h*EXT + j];
        ek_s[row*33 + j] = g_extk[(k0+row)*HH*EXT + h*EXT + j];
    }
    __syncthreads();
    int ty = tid >> 3, tx = tid & 7;    // ty: 4q, tx: 8k
    float bb = b_b[h];
    float acc[4][8];
    #pragma unroll
    for (int i = 0; i < 4; ++i)
        #pragma unroll
        for (int kk = 0; kk < 8; ++kk) acc[i][kk] = bb;
    #pragma unroll
    for (int j = 0; j < 30; ++j) {
        float qv[4], kv[8];
        #pragma unroll
        for (int i = 0; i < 4; ++i) qv[i] = eq_s[(ty*4+i)*33 + j];
        #pragma unroll
        for (int kk = 0; kk < 8; ++kk) kv[kk] = ek_s[(tx*8+kk)*33 + j];
        #pragma unroll
        for (int i = 0; i < 4; ++i)
            #pragma unroll
            for (int kk = 0; kk < 8; ++kk) acc[i][kk] += qv[i]*kv[kk];
    }
    #pragma unroll
    for (int i = 0; i < 4; ++i) {
        int q = q0 + ty*4 + i;
        float* dst = &g_att[((long)q*HH + h)*NN + k0 + tx*8];
        *reinterpret_cast<float4*>(dst)     = make_float4(acc[i][0], acc[i][1], acc[i][2], acc[i][3]);
        *reinterpret_cast<float4*>(dst + 4) = make_float4(acc[i][4], acc[i][5], acc[i][6], acc[i][7]);
    }
}

// ------------------- kernel 3: fused pair-bias + softmax + o_pair -----------
// dynamic smem (floats): wb[1536] | att[9216] | zbuf[8*772=6176]
// phase-2 partials [8][12][128]=12288 overlay att+zbuf (after att is dead)
#define FS_WB   0
#define FS_ATT  1536
#define FS_ZB   (1536+9216)
#define FS_TOT  (1536+9216+6176)   // 16928 floats = 67712 B

__global__ __launch_bounds__(256, 3)
void k_fused(const float* __restrict__ z, const float* __restrict__ mask,
             const float* __restrict__ w_b)
{
    extern __shared__ __align__(16) float sm[];
    float* wb_s  = sm + FS_WB;
    float* att_s = sm + FS_ATT;
    float* zs    = sm + FS_ZB;    // phase1: [8][772]
    __shared__ float redm[8*12];
    __shared__ float gmax[12], ginv[12];

    int q = blockIdx.x, tid = threadIdx.x;  // 256
    int wid = tid >> 5, lane = tid & 31;
    const float* zq = z + (long)q*NN*CZ;

    for (int i = tid; i < CZ*HH; i += 256) wb_s[i] = w_b[i];
    for (int i = tid; i < HH*NN; i += 256) att_s[i] = g_att[(long)q*HH*NN + i];

    // ---- phase 1: pair bias l[j][h], k = tid + 256j ----
    float l[3][12];
    #pragma unroll
    for (int j = 0; j < 3; ++j)
        #pragma unroll
        for (int h = 0; h < 12; ++h) l[j][h] = 0.f;

    for (int c0 = 0; c0 < CZ; c0 += 8) {
        __syncthreads();
        // stage [768k x 8c] transposed, coalesced global reads
        for (int f = tid; f < 1536; f += 256) {
            int k = f >> 1, c4 = f & 1;
            float4 v = *reinterpret_cast<const float4*>(zq + k*CZ + c0 + c4*4);
            zs[(c4*4+0)*772 + k] = v.x;
            zs[(c4*4+1)*772 + k] = v.y;
            zs[(c4*4+2)*772 + k] = v.z;
            zs[(c4*4+3)*772 + k] = v.w;
        }
        __syncthreads();
        #pragma unroll 2
        for (int cc = 0; cc < 8; ++cc) {
            const float* wr = &wb_s[(c0+cc)*HH];
            float z0 = zs[cc*772 + tid];
            float z1 = zs[cc*772 + tid + 256];
            float z2 = zs[cc*772 + tid + 512];
            #pragma unroll
            for (int h = 0; h < 12; ++h) {
                float wv = wr[h];
                l[0][h] += z0*wv; l[1][h] += z1*wv; l[2][h] += z2*wv;
            }
        }
    }

    // ---- combine with qkpt logits + mask + scale; track per-h max ----
    float mq = mask[q];
    float m[12];
    #pragma unroll
    for (int h = 0; h < 12; ++h) m[h] = -3.0e38f;
    #pragma unroll
    for (int j = 0; j < 3; ++j) {
        int k = tid + j*256;
        float madd = INFV * (mq*mask[k] - 1.0f);
        #pragma unroll
        for (int h = 0; h < 12; ++h) {
            float v = (att_s[h*NN + k] + l[j][h] + madd) * SQRT13;
            att_s[h*NN + k] = v;
            m[h] = fmaxf(m[h], v);
        }
    }
    // block max per head
    #pragma unroll
    for (int h = 0; h < 12; ++h)
        #pragma unroll
        for (int o = 16; o; o >>= 1) m[h] = fmaxf(m[h], __shfl_xor_sync(0xffffffffu, m[h], o));
    if (lane < 12) redm[wid*12 + lane] = m[lane];
    __syncthreads();
    if (wid == 0 && lane < 12) {
        float t = redm[lane];
        #pragma unroll
        for (int w = 1; w < 8; ++w) t = fmaxf(t, redm[w*12 + lane]);
        gmax[lane] = t;
    }
    __syncthreads();
    // exp + sum
    float s[12];
    #pragma unroll
    for (int h = 0; h < 12; ++h) s[h] = 0.f;
    #pragma unroll
    for (int j = 0; j < 3; ++j) {
        int k = tid + j*256;
        #pragma unroll
        for (int h = 0; h < 12; ++h) {
            float e = __expf(att_s[h*NN + k] - gmax[h]);
            att_s[h*NN + k] = e;
            s[h] += e;
        }
    }
    #pragma unroll
    for (int h = 0; h < 12; ++h)
        #pragma unroll
        for (int o = 16; o; o >>= 1) s[h] += __shfl_xor_sync(0xffffffffu, s[h], o);
    if (lane < 12) redm[wid*12 + lane] = s[lane];
    __syncthreads();
    if (wid == 0 && lane < 12) {
        float t = 0.f;
        #pragma unroll
        for (int w = 0; w < 8; ++w) t += redm[w*12 + lane];
        ginv[lane] = 1.f / t;
    }
    __syncthreads();
    #pragma unroll
    for (int j = 0; j < 3; ++j) {
        int k = tid + j*256;
        #pragma unroll
        for (int h = 0; h < 12; ++h) att_s[h*NN + k] *= ginv[h];
    }
    __syncthreads();

    // write softmaxed attention back for k_ov
    for (int i = tid; i < HH*NN; i += 256)
        g_att[(long)q*HH*NN + i] = att_s[i];

    // ---- phase 2: o_pair = sum_k a[h][k] * z[k][c] ----
    float4 acc[12];
    #pragma unroll
    for (int h = 0; h < 12; ++h) acc[h] = make_float4(0.f,0.f,0.f,0.f);
    const float4* zq4 = reinterpret_cast<const float4*>(zq);
    int kbeg = wid*96;
    for (int k = kbeg; k < kbeg + 96; k += 4) {
        float4 zr0 = zq4[(long)(k+0)*32 + lane];
        float4 zr1 = zq4[(long)(k+1)*32 + lane];
        float4 zr2 = zq4[(long)(k+2)*32 + lane];
        float4 zr3 = zq4[(long)(k+3)*32 + lane];
        #pragma unroll
        for (int h = 0; h < 12; ++h) {
            float a0 = att_s[h*NN + k];
            float a1 = att_s[h*NN + k + 1];
            float a2 = att_s[h*NN + k + 2];
            float a3 = att_s[h*NN + k + 3];
            acc[h].x += a0*zr0.x + a1*zr1.x + a2*zr2.x + a3*zr3.x;
            acc[h].y += a0*zr0.y + a1*zr1.y + a2*zr2.y + a3*zr3.y;
            acc[h].z += a0*zr0.z + a1*zr1.z + a2*zr2.z + a3*zr3.z;
            acc[h].w += a0*zr0.w + a1*zr1.w + a2*zr2.w + a3*zr3.w;
        }
    }
    // att_s fully consumed; overlay partials onto att region
    __syncthreads();
    float* part = sm + FS_ATT;   // [8][12][128] = 12288 floats (fits in att+zs)
    #pragma unroll
    for (int h = 0; h < 12; ++h)
        *reinterpret_cast<float4*>(&part[(wid*12 + h)*CZ + lane*4]) = acc[h];
    __syncthreads();
    for (int idx = tid; idx < HH*CZ; idx += 256) {
        int h = idx >> 7, c = idx & 127;
        float t = 0.f;
        #pragma unroll
        for (int w = 0; w < 8; ++w) t += part[(w*12 + h)*CZ + c];
        g_cat[(long)q*CATD + 576 + h*CZ + c] = t;
    }
}

// ------------------- kernel 4: o and o_pt (per-head tiled GEMM) -------------
__global__ void k_ov()
{
    __shared__ float a_t[32*68];   // [kk][q] pad 68
    __shared__ float u_t[32*44];   // [kk][j] pad 44
    int h = blockIdx.y, q0 = blockIdx.x*64;
    int tid = threadIdx.x;              // 160
    int tx = tid % 10, ty = tid / 10;   // tx: j-quad (0..9), ty: q-quad (0..15)
    float4 acc4[4];                      // acc4[i] = j-quad for q row i
    #pragma unroll
    for (int i = 0; i < 4; ++i) acc4[i] = make_float4(0.f,0.f,0.f,0.f);

    for (int kt = 0; kt < NN; kt += 32) {
        for (int idx = tid; idx < 2048; idx += 160) {
            int qq = idx >> 5, kk = idx & 31;
            a_t[kk*68 + qq] = g_att[((long)(q0+qq)*HH + h)*NN + kt + kk];
        }
        for (int idx = tid; idx < 1280; idx += 160) {
            int kk = idx / 40, j = idx % 40;
            int k = kt + kk;
            float v;
            if (j < 16) v = g_v[k*HC + h*16 + j];
            else        v = g_vpts[k*VP_DIM + h*24 + (j-16)];
            u_t[kk*44 + j] = v;
        }
        __syncthreads();
        #pragma unroll
        for (int kk = 0; kk < 32; ++kk) {
            float4 av = *reinterpret_cast<const float4*>(&a_t[kk*68 + ty*4]);
            float4 uv = *reinterpret_cast<const float4*>(&u_t[kk*44 + tx*4]);
            acc4[0].x += av.x*uv.x; acc4[0].y += av.x*uv.y; acc4[0].z += av.x*uv.z; acc4[0].w += av.x*uv.w;
            acc4[1].x += av.y*uv.x; acc4[1].y += av.y*uv.y; acc4[1].z += av.y*uv.z; acc4[1].w += av.y*uv.w;
            acc4[2].x += av.z*uv.x; acc4[2].y += av.z*uv.y; acc4[2].z += av.z*uv.z; acc4[2].w += av.z*uv.w;
            acc4[3].x += av.w*uv.x; acc4[3].y += av.w*uv.y; acc4[3].z += av.w*uv.z; acc4[3].w += av.w*uv.w;
        }
        __syncthreads();
    }
    #pragma unroll
    for (int i = 0; i < 4; ++i) {
        int q = q0 + ty*4 + i;
        float vals[4] = {acc4[i].x, acc4[i].y, acc4[i].z, acc4[i].w};
        #pragma unroll
        for (int jj = 0; jj < 4; ++jj) {
            int j = tx*4 + jj;
            if (j < 16) g_cat[(long)q*CATD + h*16 + j] = vals[jj];
            else        g_opt[q*VP_DIM + h*24 + (j-16)] = vals[jj];
        }
    }
}

// ------------------- kernel 4b: inverse rigid + norm ------------------------
__global__ void k_rigid(const float* __restrict__ rot, const float* __restrict__ trans)
{
    int q = blockIdx.x, m = threadIdx.x;   // 96 threads
    float x = g_opt[q*VP_DIM + m*3+0] - trans[q*3+0];
    float y = g_opt[q*VP_DIM + m*3+1] - trans[q*3+1];
    float w = g_opt[q*VP_DIM + m*3+2] - trans[q*3+2];
    const float* R = rot + q*9;
    float l0 = R[0]*x + R[3]*y + R[6]*w;
    float l1 = R[1]*x + R[4]*y + R[7]*w;
    float l2 = R[2]*x + R[5]*y + R[8]*w;
    g_cat[(long)q*CATD + 192 + m] = l0;
    g_cat[(long)q*CATD + 288 + m] = l1;
    g_cat[(long)q*CATD + 384 + m] = l2;
    g_cat[(long)q*CATD + 480 + m] = sqrtf(l0*l0 + l1*l1 + l2*l2 + 1e-8f);
}

// ------------------- kernel 5: final output GEMM ----------------------------
__global__ void k_final(const float* __restrict__ w_o, const float* __restrict__ b_o,
                        float* __restrict__ out)
{
    __shared__ float a_t[32*33];
    __shared__ float b_t[32*68];
    int q0 = blockIdx.x*32, n0b = blockIdx.y*64;
    int tid = threadIdx.x;              // 256
    int tx = tid & 15, ty = tid >> 4;   // tx: 4 n (float4), ty(0..15): 2 q
    float4 acc[2];
    acc[0] = make_float4(0.f,0.f,0.f,0.f);
    acc[1] = make_float4(0.f,0.f,0.f,0.f);

    for (int kt = 0; kt < CATD; kt += 32) {
        for (int idx = tid; idx < 1024; idx += 256) {
            int qq = idx >> 5, kk = idx & 31;
            a_t[kk*33 + qq] = g_cat[(long)(q0+qq)*CATD + kt + kk];
        }
        for (int idx = tid; idx < 2048; idx += 256) {
            int kk = idx >> 6, nn = idx & 63;
            b_t[kk*68 + nn] = w_o[(kt+kk)*CS + n0b + nn];
        }
        __syncthreads();
        #pragma unroll
        for (int kk = 0; kk < 32; ++kk) {
            float av0 = a_t[kk*33 + ty*2 + 0];
            float av1 = a_t[kk*33 + ty*2 + 1];
            float4 bv = *reinterpret_cast<const float4*>(&b_t[kk*68 + tx*4]);
            acc[0].x += av0*bv.x; acc[0].y += av0*bv.y; acc[0].z += av0*bv.z; acc[0].w += av0*bv.w;
            acc[1].x += av1*bv.x; acc[1].y += av1*bv.y; acc[1].z += av1*bv.z; acc[1].w += av1*bv.w;
        }
        __syncthreads();
    }
    float4 bia = *reinterpret_cast<const float4*>(&b_o[n0b + tx*4]);
    #pragma unroll
    for (int i = 0; i < 2; ++i) {
        int q = q0 + ty*2 + i;
        float4 r = acc[i];
        r.x += bia.x; r.y += bia.y; r.z += bia.z; r.w += bia.w;
        *reinterpret_cast<float4*>(&out[q*CS + n0b + tx*4]) = r;
    }
}

// ------------------- launcher ----------------------------------------------
extern "C" void kernel_launch(void* const* d_in, const int* in_sizes, int n_in,
                              void* d_out, int out_size)
{
    const float* s     = (const float*)d_in[0];
    const float* z     = (const float*)d_in[1];
    const float* rot   = (const float*)d_in[2];
    const float* trans = (const float*)d_in[3];
    const float* mask  = (const float*)d_in[4];
    const float* w_q   = (const float*)d_in[5];
    const float* b_q   = (const float*)d_in[6];
    const float* w_k   = (const float*)d_in[7];
    const float* b_k   = (const float*)d_in[8];
    const float* w_v   = (const float*)d_in[9];
    const float* b_v   = (const float*)d_in[10];
    const float* w_qp  = (const float*)d_in[11];
    const float* b_qp  = (const float*)d_in[12];
    const float* w_kp  = (const float*)d_in[13];
    const float* b_kp  = (const float*)d_in[14];
    const float* w_vp  = (const float*)d_in[15];
    const float* b_vp  = (const float*)d_in[16];
    const float* w_b   = (const float*)d_in[17];
    const float* b_b   = (const float*)d_in[18];
    const float* hw    = (const float*)d_in[19];
    const float* w_o   = (const float*)d_in[20];
    const float* b_o   = (const float*)d_in[21];
    float* out = (float*)d_out;

    cudaFuncSetAttribute(k_fused, cudaFuncAttributeMaxDynamicSharedMemorySize, FS_TOT*4);

    k_gproj<<<dim3(12, 18), 256>>>(s, w_q,b_q,w_k,b_k,w_v,b_v,w_qp,b_qp,w_kp,b_kp,w_vp,b_vp);
    k_post<<<NN, 256>>>(rot, trans, hw);
    k_qkpt<<<dim3(12, 12, 12), 128>>>(b_b);
    k_fused<<<NN, 256, FS_TOT*4>>>(z, mask, w_b);
    k_ov<<<dim3(12, HH), 160>>>();
    k_rigid<<<NN, 96>>>(rot, trans);
    k_final<<<dim3(24, 6), 256>>>(w_o, b_o, out);
}

// round 11
// speedup vs baseline: 1.1616x; 1.1616x over previous
#include <cuda_runtime.h>
#include <math.h>

#define NN 768
#define CS 384
#define CZ 128
#define CH 16
#define HH 12
#define PQK 4
#define PV 8
#define HC (HH*CH)        // 192
#define VP_DIM (HH*3*PV)  // 288
#define CATD 2112
#define OTOT 1152
#define INFV 100000.0f
#define SQRT13 0.57735026918962576f
#define EXT 32

// ------------------- scratch ------------------------------------------------
__device__ float g_raw[NN*OTOT];
__device__ float g_v[NN*HC];
__device__ float g_vpts[NN*VP_DIM];
__device__ float g_extq[NN*HH*EXT];
__device__ float g_extk[NN*HH*EXT];
__device__ float g_att[NN*HH*NN];   // [q][h][k]
__device__ float g_opt[NN*VP_DIM];
__device__ float g_cat[NN*CATD];

// ------------------- kernel 1: big projection GEMM --------------------------
struct WSrc { const float* w; const float* b; int lo; int F; };

__device__ __forceinline__ WSrc wmap(int o,
    const float* w_q, const float* b_q, const float* w_k, const float* b_k,
    const float* w_v, const float* b_v, const float* w_qp, const float* b_qp,
    const float* w_kp, const float* b_kp, const float* w_vp, const float* b_vp)
{
    WSrc r;
    if (o < 192)      { r.w = w_q;  r.b = b_q;  r.lo = o;       r.F = 192; }
    else if (o < 384) { r.w = w_k;  r.b = b_k;  r.lo = o - 192; r.F = 192; }
    else if (o < 576) { r.w = w_v;  r.b = b_v;  r.lo = o - 384; r.F = 192; }
    else if (o < 720) { r.w = w_qp; r.b = b_qp; r.lo = o - 576; r.F = 144; }
    else if (o < 864) { r.w = w_kp; r.b = b_kp; r.lo = o - 720; r.F = 144; }
    else              { r.w = w_vp; r.b = b_vp; r.lo = o - 864; r.F = 288; }
    return r;
}

__global__ void k_gproj(const float* __restrict__ s,
    const float* __restrict__ w_q, const float* __restrict__ b_q,
    const float* __restrict__ w_k, const float* __restrict__ b_k,
    const float* __restrict__ w_v, const float* __restrict__ b_v,
    const float* __restrict__ w_qp, const float* __restrict__ b_qp,
    const float* __restrict__ w_kp, const float* __restrict__ b_kp,
    const float* __restrict__ w_vp, const float* __restrict__ b_vp)
{
    __shared__ float a_t[32*68];
    __shared__ float b_t[32*68];
    __shared__ float bias_s[64];
    int n0 = blockIdx.x*64, o0 = blockIdx.y*64;
    int tid = threadIdx.x;                 // 256
    int tx = tid & 15, ty = tid >> 4;      // tx: 4 o (float4), ty: 4 n

    if (tid < 64) {
        WSrc m = wmap(o0 + tid, w_q,b_q,w_k,b_k,w_v,b_v,w_qp,b_qp,w_kp,b_kp,w_vp,b_vp);
        bias_s[tid] = m.b[m.lo];
    }

    float4 acc[4];
    #pragma unroll
    for (int i = 0; i < 4; ++i) acc[i] = make_float4(0.f,0.f,0.f,0.f);

    for (int kt = 0; kt < CS; kt += 32) {
        __syncthreads();
        for (int idx = tid; idx < 2048; idx += 256) {
            int nn = idx >> 5, kk = idx & 31;
            a_t[kk*68 + nn] = s[(n0+nn)*CS + kt + kk];
        }
        for (int idx = tid; idx < 2048; idx += 256) {
            int kk = idx >> 6, oo = idx & 63;
            WSrc m = wmap(o0 + oo, w_q,b_q,w_k,b_k,w_v,b_v,w_qp,b_qp,w_kp,b_kp,w_vp,b_vp);
            b_t[kk*68 + oo] = m.w[(kt+kk)*m.F + m.lo];
        }
        __syncthreads();
        #pragma unroll
        for (int kk = 0; kk < 32; ++kk) {
            float av[4];
            #pragma unroll
            for (int i = 0; i < 4; ++i) av[i] = a_t[kk*68 + ty*4 + i];
            float4 bv = *reinterpret_cast<const float4*>(&b_t[kk*68 + tx*4]);
            #pragma unroll
            for (int i = 0; i < 4; ++i) {
                acc[i].x += av[i]*bv.x; acc[i].y += av[i]*bv.y;
                acc[i].z += av[i]*bv.z; acc[i].w += av[i]*bv.w;
            }
        }
    }
    float4 bia = *reinterpret_cast<const float4*>(&bias_s[tx*4]);
    #pragma unroll
    for (int i = 0; i < 4; ++i) {
        int n = n0 + ty*4 + i;
        float4 r = acc[i];
        r.x += bia.x; r.y += bia.y; r.z += bia.z; r.w += bia.w;
        *reinterpret_cast<float4*>(&g_raw[n*OTOT + o0 + tx*4]) = r;
    }
}

// ------------------- kernel 1b: rigid transform + ext features --------------
__global__ void k_post(const float* __restrict__ rot, const float* __restrict__ trans,
                       const float* __restrict__ head_weights)
{
    __shared__ float raw[OTOT];
    __shared__ float rt_s[9], tr_s[3];
    __shared__ float qg[48*3], kg[48*3];
    __shared__ float q2p[48], k2p[48];
    __shared__ float q2s[12], k2s[12], pw_s[12];
    int n = blockIdx.x, tid = threadIdx.x;  // 256
    for (int i = tid; i < OTOT; i += 256) raw[i] = g_raw[n*OTOT + i];
    if (tid < 9) rt_s[tid] = rot[n*9 + tid];
    if (tid < 3) tr_s[tid] = trans[n*3 + tid];
    __syncthreads();

    if (tid < 192) g_v[n*HC + tid] = raw[384 + tid];

    if (tid < 192) {
        int it = tid;
        const float* src; int h, p, P; int tag;
        if (it < 48)      { src = raw + 576; h = it/4; p = it%4; P = 4; tag = 0; }
        else if (it < 96) { it -= 48; src = raw + 720; h = it/4; p = it%4; P = 4; tag = 1; }
        else              { it -= 96; src = raw + 864; h = it/8; p = it%8; P = 8; tag = 2; }
        float l0 = src[h*3*P + 0*P + p];
        float l1 = src[h*3*P + 1*P + p];
        float l2 = src[h*3*P + 2*P + p];
        float gx = rt_s[0]*l0 + rt_s[1]*l1 + rt_s[2]*l2 + tr_s[0];
        float gy = rt_s[3]*l0 + rt_s[4]*l1 + rt_s[5]*l2 + tr_s[1];
        float gz = rt_s[6]*l0 + rt_s[7]*l1 + rt_s[8]*l2 + tr_s[2];
        if (tag == 2) {
            int base = ((n*HH + h)*P + p)*3;
            g_vpts[base+0] = gx; g_vpts[base+1] = gy; g_vpts[base+2] = gz;
        } else {
            float* dst = (tag == 0) ? qg : kg;
            dst[(h*4+p)*3+0] = gx; dst[(h*4+p)*3+1] = gy; dst[(h*4+p)*3+2] = gz;
            float n2 = gx*gx + gy*gy + gz*gz;
            if (tag == 0) q2p[h*4+p] = n2; else k2p[h*4+p] = n2;
        }
    }
    __syncthreads();
    if (tid < 12) {
        q2s[tid] = q2p[tid*4] + q2p[tid*4+1] + q2p[tid*4+2] + q2p[tid*4+3];
        k2s[tid] = k2p[tid*4] + k2p[tid*4+1] + k2p[tid*4+2] + k2p[tid*4+3];
        float x = head_weights[tid];
        float sp = fmaxf(x, 0.f) + log1pf(expf(-fabsf(x)));
        pw_s[tid] = 0.23570226039551584f * sp;   // sqrt(2/36)*softplus
    }
    __syncthreads();

    for (int idx = tid; idx < HH*EXT; idx += 256) {
        int h = idx >> 5, j = idx & 31;
        float pw = pw_s[h];
        float eq = 0.f, ek = 0.f;
        if (j < 16) {
            eq = raw[h*16 + j] * 0.25f;
            ek = raw[192 + h*16 + j];
        } else if (j < 28) {
            int p = (j-16)/3, c = (j-16)%3;
            eq = pw * qg[(h*4+p)*3 + c];
            ek = kg[(h*4+p)*3 + c];
        } else if (j == 28) {
            eq = -0.5f * pw * q2s[h];  ek = 1.f;
        } else if (j == 29) {
            eq = 1.f;  ek = -0.5f * pw * k2s[h];
        }
        g_extq[n*HH*EXT + idx] = eq;
        g_extk[n*HH*EXT + idx] = ek;
    }
}

// ------------------- kernel 2: ext-dot (qk + point attention) ---------------
__global__ void k_qkpt(const float* __restrict__ b_b)
{
    __shared__ float eq_s[64*33];
    __shared__ float ek_s[64*33];
    int kt = blockIdx.x, qt = blockIdx.y, h = blockIdx.z;
    int q0 = qt*64, k0 = kt*64;
    int tid = threadIdx.x;              // 128
    for (int idx = tid; idx < 64*32; idx += 128) {
        int row = idx >> 5, j = idx & 31;
        eq_s[row*33 + j] = g_extq[(q0+row)*HH*EXT + h*EXT + j];
        ek_s[row*33 + j] = g_extk[(k0+row)*HH*EXT + h*EXT + j];
    }
    __syncthreads();
    int ty = tid >> 3, tx = tid & 7;    // ty: 4q, tx: 8k
    float bb = b_b[h];
    float acc[4][8];
    #pragma unroll
    for (int i = 0; i < 4; ++i)
        #pragma unroll
        for (int kk = 0; kk < 8; ++kk) acc[i][kk] = bb;
    #pragma unroll
    for (int j = 0; j < 30; ++j) {
        float qv[4], kv[8];
        #pragma unroll
        for (int i = 0; i < 4; ++i) qv[i] = eq_s[(ty*4+i)*33 + j];
        #pragma unroll
        for (int kk = 0; kk < 8; ++kk) kv[kk] = ek_s[(tx*8+kk)*33 + j];
        #pragma unroll
        for (int i = 0; i < 4; ++i)
            #pragma unroll
            for (int kk = 0; kk < 8; ++kk) acc[i][kk] += qv[i]*kv[kk];
    }
    #pragma unroll
    for (int i = 0; i < 4; ++i) {
        int q = q0 + ty*4 + i;
        float* dst = &g_att[((long)q*HH + h)*NN + k0 + tx*8];
        *reinterpret_cast<float4*>(dst)     = make_float4(acc[i][0], acc[i][1], acc[i][2], acc[i][3]);
        *reinterpret_cast<float4*>(dst + 4) = make_float4(acc[i][4], acc[i][5], acc[i][6], acc[i][7]);
    }
}

// ------------------- kernel 3: fused pair-bias + softmax + o_pair -----------
// dynamic smem: wb[1536] | att[9216] | zbuf[12352 floats, aliased as part 8*12*128]
#define FS_WB   0
#define FS_ATT  1536
#define FS_ZB   (1536+9216)
#define FS_TOT  (1536+9216+12352)

__global__ void k_fused(const float* __restrict__ z, const float* __restrict__ mask,
                        const float* __restrict__ w_b)
{
    extern __shared__ __align__(16) float sm[];
    float* wb_s  = sm + FS_WB;
    float* att_s = sm + FS_ATT;
    float* zs    = sm + FS_ZB;    // phase1: [16][772]; phase2: part [8][12][128]
    __shared__ float redm[8*12];
    __shared__ float gmax[12], ginv[12];

    int q = blockIdx.x, tid = threadIdx.x;  // 256
    int wid = tid >> 5, lane = tid & 31;
    const float* zq = z + (long)q*NN*CZ;

    for (int i = tid; i < CZ*HH; i += 256) wb_s[i] = w_b[i];
    for (int i = tid; i < HH*NN; i += 256) att_s[i] = g_att[(long)q*HH*NN + i];

    // ---- phase 1: pair bias l[j][h], k = tid + 256j ----
    float l[3][12];
    #pragma unroll
    for (int j = 0; j < 3; ++j)
        #pragma unroll
        for (int h = 0; h < 12; ++h) l[j][h] = 0.f;

    for (int c0 = 0; c0 < CZ; c0 += 16) {
        __syncthreads();
        for (int f = tid; f < 3072; f += 256) {
            int k = f >> 2, c4 = f & 3;
            float4 v = *reinterpret_cast<const float4*>(zq + k*CZ + c0 + c4*4);
            zs[(c4*4+0)*772 + k] = v.x;
            zs[(c4*4+1)*772 + k] = v.y;
            zs[(c4*4+2)*772 + k] = v.z;
            zs[(c4*4+3)*772 + k] = v.w;
        }
        __syncthreads();
        #pragma unroll 2
        for (int cc = 0; cc < 16; ++cc) {
            const float* wr = &wb_s[(c0+cc)*HH];
            float z0 = zs[cc*772 + tid];
            float z1 = zs[cc*772 + tid + 256];
            float z2 = zs[cc*772 + tid + 512];
            #pragma unroll
            for (int h = 0; h < 12; ++h) {
                float wv = wr[h];
                l[0][h] += z0*wv; l[1][h] += z1*wv; l[2][h] += z2*wv;
            }
        }
    }

    // ---- combine with qkpt logits + mask + scale; track per-h max ----
    float mq = mask[q];
    float m[12];
    #pragma unroll
    for (int h = 0; h < 12; ++h) m[h] = -3.0e38f;
    #pragma unroll
    for (int j = 0; j < 3; ++j) {
        int k = tid + j*256;
        float madd = INFV * (mq*mask[k] - 1.0f);
        #pragma unroll
        for (int h = 0; h < 12; ++h) {
            float v = (att_s[h*NN + k] + l[j][h] + madd) * SQRT13;
            att_s[h*NN + k] = v;
            m[h] = fmaxf(m[h], v);
        }
    }
    // block max per head
    #pragma unroll
    for (int h = 0; h < 12; ++h)
        #pragma unroll
        for (int o = 16; o; o >>= 1) m[h] = fmaxf(m[h], __shfl_xor_sync(0xffffffffu, m[h], o));
    if (lane < 12) redm[wid*12 + lane] = m[lane];
    __syncthreads();
    if (wid == 0 && lane < 12) {
        float t = redm[lane];
        #pragma unroll
        for (int w = 1; w < 8; ++w) t = fmaxf(t, redm[w*12 + lane]);
        gmax[lane] = t;
    }
    __syncthreads();
    // exp + sum
    float s[12];
    #pragma unroll
    for (int h = 0; h < 12; ++h) s[h] = 0.f;
    #pragma unroll
    for (int j = 0; j < 3; ++j) {
        int k = tid + j*256;
        #pragma unroll
        for (int h = 0; h < 12; ++h) {
            float e = __expf(att_s[h*NN + k] - gmax[h]);
            att_s[h*NN + k] = e;
            s[h] += e;
        }
    }
    #pragma unroll
    for (int h = 0; h < 12; ++h)
        #pragma unroll
        for (int o = 16; o; o >>= 1) s[h] += __shfl_xor_sync(0xffffffffu, s[h], o);
    if (lane < 12) redm[wid*12 + lane] = s[lane];
    __syncthreads();
    if (wid == 0 && lane < 12) {
        float t = 0.f;
        #pragma unroll
        for (int w = 0; w < 8; ++w) t += redm[w*12 + lane];
        ginv[lane] = 1.f / t;
    }
    __syncthreads();
    #pragma unroll
    for (int j = 0; j < 3; ++j) {
        int k = tid + j*256;
        #pragma unroll
        for (int h = 0; h < 12; ++h) att_s[h*NN + k] *= ginv[h];
    }
    __syncthreads();

    // write softmaxed attention back for k_ov
    for (int i = tid; i < HH*NN; i += 256)
        g_att[(long)q*HH*NN + i] = att_s[i];

    // ---- phase 2: o_pair = sum_k a[h][k] * z[k][c] ----
    float* part = zs;   // [8][12][128]
    float4 acc[12];
    #pragma unroll
    for (int h = 0; h < 12; ++h) acc[h] = make_float4(0.f,0.f,0.f,0.f);
    const float4* zq4 = reinterpret_cast<const float4*>(zq);
    int kbeg = wid*96;
    for (int k = kbeg; k < kbeg + 96; k += 4) {
        float4 zr0 = zq4[(long)(k+0)*32 + lane];
        float4 zr1 = zq4[(long)(k+1)*32 + lane];
        float4 zr2 = zq4[(long)(k+2)*32 + lane];
        float4 zr3 = zq4[(long)(k+3)*32 + lane];
        #pragma unroll
        for (int h = 0; h < 12; ++h) {
            float a0 = att_s[h*NN + k];
            float a1 = att_s[h*NN + k + 1];
            float a2 = att_s[h*NN + k + 2];
            float a3 = att_s[h*NN + k + 3];
            acc[h].x += a0*zr0.x + a1*zr1.x + a2*zr2.x + a3*zr3.x;
            acc[h].y += a0*zr0.y + a1*zr1.y + a2*zr2.y + a3*zr3.y;
            acc[h].z += a0*zr0.z + a1*zr1.z + a2*zr2.z + a3*zr3.z;
            acc[h].w += a0*zr0.w + a1*zr1.w + a2*zr2.w + a3*zr3.w;
        }
    }
    #pragma unroll
    for (int h = 0; h < 12; ++h)
        *reinterpret_cast<float4*>(&part[(wid*12 + h)*CZ + lane*4]) = acc[h];
    __syncthreads();
    for (int idx = tid; idx < HH*CZ; idx += 256) {
        int h = idx >> 7, c = idx & 127;
        float t = 0.f;
        #pragma unroll
        for (int w = 0; w < 8; ++w) t += part[(w*12 + h)*CZ + c];
        g_cat[(long)q*CATD + 576 + h*CZ + c] = t;
    }
}

// ------------------- kernel 4: o and o_pt (per-head tiled GEMM) -------------
__global__ void k_ov()
{
    __shared__ float a_t[32*68];   // [kk][q] pad 68
    __shared__ float u_t[32*44];   // [kk][j] pad 44
    int h = blockIdx.y, q0 = blockIdx.x*64;
    int tid = threadIdx.x;              // 160
    int tx = tid % 10, ty = tid / 10;   // tx: j-quad (0..9), ty: q-quad (0..15)
    float4 acc4[4];                      // acc4[i] = j-quad for q row i
    #pragma unroll
    for (int i = 0; i < 4; ++i) acc4[i] = make_float4(0.f,0.f,0.f,0.f);

    for (int kt = 0; kt < NN; kt += 32) {
        for (int idx = tid; idx < 2048; idx += 160) {
            int qq = idx >> 5, kk = idx & 31;
            a_t[kk*68 + qq] = g_att[((long)(q0+qq)*HH + h)*NN + kt + kk];
        }
        for (int idx = tid; idx < 1280; idx += 160) {
            int kk = idx / 40, j = idx % 40;
            int k = kt + kk;
            float v;
            if (j < 16) v = g_v[k*HC + h*16 + j];
            else        v = g_vpts[k*VP_DIM + h*24 + (j-16)];
            u_t[kk*44 + j] = v;
        }
        __syncthreads();
        #pragma unroll
        for (int kk = 0; kk < 32; ++kk) {
            float4 av = *reinterpret_cast<const float4*>(&a_t[kk*68 + ty*4]);
            float4 uv = *reinterpret_cast<const float4*>(&u_t[kk*44 + tx*4]);
            acc4[0].x += av.x*uv.x; acc4[0].y += av.x*uv.y; acc4[0].z += av.x*uv.z; acc4[0].w += av.x*uv.w;
            acc4[1].x += av.y*uv.x; acc4[1].y += av.y*uv.y; acc4[1].z += av.y*uv.z; acc4[1].w += av.y*uv.w;
            acc4[2].x += av.z*uv.x; acc4[2].y += av.z*uv.y; acc4[2].z += av.z*uv.z; acc4[2].w += av.z*uv.w;
            acc4[3].x += av.w*uv.x; acc4[3].y += av.w*uv.y; acc4[3].z += av.w*uv.z; acc4[3].w += av.w*uv.w;
        }
        __syncthreads();
    }
    #pragma unroll
    for (int i = 0; i < 4; ++i) {
        int q = q0 + ty*4 + i;
        float vals[4] = {acc4[i].x, acc4[i].y, acc4[i].z, acc4[i].w};
        #pragma unroll
        for (int jj = 0; jj < 4; ++jj) {
            int j = tx*4 + jj;
            if (j < 16) g_cat[(long)q*CATD + h*16 + j] = vals[jj];
            else        g_opt[q*VP_DIM + h*24 + (j-16)] = vals[jj];
        }
    }
}

// ------------------- kernel 4b: inverse rigid + norm ------------------------
__global__ void k_rigid(const float* __restrict__ rot, const float* __restrict__ trans)
{
    int q = blockIdx.x, m = threadIdx.x;   // 96 threads
    float x = g_opt[q*VP_DIM + m*3+0] - trans[q*3+0];
    float y = g_opt[q*VP_DIM + m*3+1] - trans[q*3+1];
    float w = g_opt[q*VP_DIM + m*3+2] - trans[q*3+2];
    const float* R = rot + q*9;
    float l0 = R[0]*x + R[3]*y + R[6]*w;
    float l1 = R[1]*x + R[4]*y + R[7]*w;
    float l2 = R[2]*x + R[5]*y + R[8]*w;
    g_cat[(long)q*CATD + 192 + m] = l0;
    g_cat[(long)q*CATD + 288 + m] = l1;
    g_cat[(long)q*CATD + 384 + m] = l2;
    g_cat[(long)q*CATD + 480 + m] = sqrtf(l0*l0 + l1*l1 + l2*l2 + 1e-8f);
}

// ------------------- kernel 5: final output GEMM (64x64, 4x4 microtile) -----
__global__ void k_final(const float* __restrict__ w_o, const float* __restrict__ b_o,
                        float* __restrict__ out)
{
    __shared__ float a_t[32*68];
    __shared__ float b_t[32*68];
    int q0 = blockIdx.x*64, n0b = blockIdx.y*64;
    int tid = threadIdx.x;              // 256
    int tx = tid & 15, ty = tid >> 4;   // tx: n-quad, ty: q-quad
    float4 acc4[4];
    #pragma unroll
    for (int i = 0; i < 4; ++i) acc4[i] = make_float4(0.f,0.f,0.f,0.f);

    for (int kt = 0; kt < CATD; kt += 32) {
        for (int idx = tid; idx < 2048; idx += 256) {
            int qq = idx >> 5, kk = idx & 31;
            a_t[kk*68 + qq] = g_cat[(long)(q0+qq)*CATD + kt + kk];
        }
        for (int idx = tid; idx < 2048; idx += 256) {
            int kk = idx >> 6, nn = idx & 63;
            b_t[kk*68 + nn] = w_o[(kt+kk)*CS + n0b + nn];
        }
        __syncthreads();
        #pragma unroll
        for (int kk = 0; kk < 32; ++kk) {
            float4 av = *reinterpret_cast<const float4*>(&a_t[kk*68 + ty*4]);
            float4 bv = *reinterpret_cast<const float4*>(&b_t[kk*68 + tx*4]);
            acc4[0].x += av.x*bv.x; acc4[0].y += av.x*bv.y; acc4[0].z += av.x*bv.z; acc4[0].w += av.x*bv.w;
            acc4[1].x += av.y*bv.x; acc4[1].y += av.y*bv.y; acc4[1].z += av.y*bv.z; acc4[1].w += av.y*bv.w;
            acc4[2].x += av.z*bv.x; acc4[2].y += av.z*bv.y; acc4[2].z += av.z*bv.z; acc4[2].w += av.z*bv.w;
            acc4[3].x += av.w*bv.x; acc4[3].y += av.w*bv.y; acc4[3].z += av.w*bv.z; acc4[3].w += av.w*bv.w;
        }
        __syncthreads();
    }
    float4 bia = *reinterpret_cast<const float4*>(&b_o[n0b + tx*4]);
    #pragma unroll
    for (int i = 0; i < 4; ++i) {
        int q = q0 + ty*4 + i;
        float4 r = acc4[i];
        r.x += bia.x; r.y += bia.y; r.z += bia.z; r.w += bia.w;
        *reinterpret_cast<float4*>(&out[q*CS + n0b + tx*4]) = r;
    }
}

// ------------------- launcher ----------------------------------------------
extern "C" void kernel_launch(void* const* d_in, const int* in_sizes, int n_in,
                              void* d_out, int out_size)
{
    const float* s     = (const float*)d_in[0];
    const float* z     = (const float*)d_in[1];
    const float* rot   = (const float*)d_in[2];
    const float* trans = (const float*)d_in[3];
    const float* mask  = (const float*)d_in[4];
    const float* w_q   = (const float*)d_in[5];
    const float* b_q   = (const float*)d_in[6];
    const float* w_k   = (const float*)d_in[7];
    const float* b_k   = (const float*)d_in[8];
    const float* w_v   = (const float*)d_in[9];
    const float* b_v   = (const float*)d_in[10];
    const float* w_qp  = (const float*)d_in[11];
    const float* b_qp  = (const float*)d_in[12];
    const float* w_kp  = (const float*)d_in[13];
    const float* b_kp  = (const float*)d_in[14];
    const float* w_vp  = (const float*)d_in[15];
    const float* b_vp  = (const float*)d_in[16];
    const float* w_b   = (const float*)d_in[17];
    const float* b_b   = (const float*)d_in[18];
    const float* hw    = (const float*)d_in[19];
    const float* w_o   = (const float*)d_in[20];
    const float* b_o   = (const float*)d_in[21];
    float* out = (float*)d_out;

    cudaFuncSetAttribute(k_fused, cudaFuncAttributeMaxDynamicSharedMemorySize, FS_TOT*4);

    k_gproj<<<dim3(12, 18), 256>>>(s, w_q,b_q,w_k,b_k,w_v,b_v,w_qp,b_qp,w_kp,b_kp,w_vp,b_vp);
    k_post<<<NN, 256>>>(rot, trans, hw);
    k_qkpt<<<dim3(12, 12, 12), 128>>>(b_b);
    k_fused<<<NN, 256, FS_TOT*4>>>(z, mask, w_b);
    k_ov<<<dim3(12, HH), 160>>>();
    k_rigid<<<NN, 96>>>(rot, trans);
    k_final<<<dim3(12, 6), 256>>>(w_o, b_o, out);
}